// round 7
// baseline (speedup 1.0000x reference)
#include <cuda_runtime.h>
#include <cuda_bf16.h>

// Problem constants: N=50000 nodes, E=1.6M edges, D_in=D_out=128.
#define D 128
#define D4 (D / 4)              // 32 float4 per row
#define MAX_NODES 50048
#define CAP 128                 // bucket capacity (Poisson(32); overflow astronomically rare)
#define K_TOT 256               // concat [feat ; mean_neigh]
#define BM 64                   // nodes per block in GEMM
#define ZT_STRIDE 68            // padded row stride for transposed Z tile (68*4 % 16 == 0)

// ---------------- scratch (device globals) ----------------
__device__ float          g_agg[MAX_NODES * D];       // neighbor mean
__device__ int            g_cnt[MAX_NODES];           // in-degree
__device__ int            g_bucket[MAX_NODES * CAP];  // per-node src ids
__device__ __nv_bfloat16  g_featbf[MAX_NODES * D];    // bf16 copy of feat (gather operand)
__device__ float          g_wt[K_TOT * D];            // Wcat^T: g_wt[k][o]
__device__ float          g_bias[D];                  // b_self + b_neigh

// ---------------- packed f32x2 helpers ----------------
__device__ __forceinline__ unsigned long long pack2_dup(float x) {
    unsigned long long r;
    asm("mov.b64 %0, {%1, %1};" : "=l"(r) : "f"(x));
    return r;
}
__device__ __forceinline__ void ffma2(unsigned long long& acc,
                                      unsigned long long a, unsigned long long b) {
    asm("fma.rn.f32x2 %0, %1, %2, %0;" : "+l"(acc) : "l"(a), "l"(b));
}
__device__ __forceinline__ void unpack2(unsigned long long v, float& lo, float& hi) {
    asm("mov.b64 {%0, %1}, %2;" : "=f"(lo), "=f"(hi) : "l"(v));
}

// ---------------- kernel: zero in-degree counters ----------------
__global__ void zero_kernel(int n_cnt) {
    int i = blockIdx.x * blockDim.x + threadIdx.x;
    if (i < n_cnt) g_cnt[i] = 0;
}

// ---------------- kernel: convert feat -> bf16 ----------------
__global__ void convert_kernel(const float* __restrict__ feat, int n_f2) {
    int i = blockIdx.x * blockDim.x + threadIdx.x;
    if (i >= n_f2) return;
    float2 f = reinterpret_cast<const float2*>(feat)[i];
    reinterpret_cast<__nv_bfloat162*>(g_featbf)[i] = __float22bfloat162_rn(f);
}

// ---------------- kernel: prep transposed concat weights + fused bias ----------------
__global__ void prep_kernel(const float* __restrict__ W_self,
                            const float* __restrict__ W_neigh,
                            const float* __restrict__ b_self,
                            const float* __restrict__ b_neigh) {
    int i = blockIdx.x * blockDim.x + threadIdx.x;   // 0 .. 16383
    if (i < D * D) {
        int k = i >> 7;          // input index
        int o = i & (D - 1);     // output index (fast-varying -> coalesced stores)
        g_wt[k * D + o]       = W_self[o * D + k];
        g_wt[(k + D) * D + o] = W_neigh[o * D + k];
    }
    if (i < D) g_bias[i] = b_self[i] + b_neigh[i];
}

// ---------------- kernel: fill per-dst buckets with src ids ----------------
__global__ void fill_kernel(const int* __restrict__ src,
                            const int* __restrict__ dst,
                            int n_edges) {
    int e = blockIdx.x * blockDim.x + threadIdx.x;
    if (e >= n_edges) return;
    int s = src[e];
    int d = dst[e];
    int pos = atomicAdd(&g_cnt[d], 1);
    if (pos < CAP) g_bucket[d * CAP + pos] = s;
    // pos >= CAP: handled by rescan fallback in aggregate_kernel (never in practice)
}

// ---------------- kernel: warp-per-node pull aggregation (bf16 gather, fp32 accum) ----------------
__global__ void aggregate_kernel(const float* __restrict__ feat,
                                 const int* __restrict__ src,
                                 const int* __restrict__ dst,
                                 int n_nodes, int n_edges) {
    int w = (blockIdx.x * blockDim.x + threadIdx.x) >> 5;
    if (w >= n_nodes) return;
    int lane = threadIdx.x & 31;

    int c = g_cnt[w];
    float acc0 = 0.f, acc1 = 0.f, acc2 = 0.f, acc3 = 0.f;

    if (c <= CAP) {
        // fast path: pull bf16 rows listed in the bucket
        const uint2* fb = reinterpret_cast<const uint2*>(g_featbf);  // 4 bf16 per 8B? -> uint2 = 4 cols
        const int* bk = &g_bucket[w * CAP];
        for (int i0 = 0; i0 < c; i0 += 32) {
            int take = min(32, c - i0);
            int my = (lane < take) ? bk[i0 + lane] : 0;
            #pragma unroll 4
            for (int j = 0; j < take; j++) {
                int s = __shfl_sync(0xffffffffu, my, j);
                // lane covers cols [4*lane, 4*lane+4): 4 bf16 = 8 bytes = one uint2
                uint2 v = __ldg(&fb[(size_t)s * 32 + lane]);
                float2 p0 = __bfloat1622float2(*reinterpret_cast<__nv_bfloat162*>(&v.x));
                float2 p1 = __bfloat1622float2(*reinterpret_cast<__nv_bfloat162*>(&v.y));
                acc0 += p0.x; acc1 += p0.y; acc2 += p1.x; acc3 += p1.y;
            }
        }
    } else {
        // correctness fallback (statistically never): rescan full edge list, fp32 gather
        const float4* f4 = reinterpret_cast<const float4*>(feat);
        for (int e = 0; e < n_edges; e++) {
            if (dst[e] == w) {
                float4 v = f4[(size_t)src[e] * D4 + lane];
                acc0 += v.x; acc1 += v.y; acc2 += v.z; acc3 += v.w;
            }
        }
    }

    float inv = 1.0f / fmaxf((float)c, 1.0f);
    float4* a4 = reinterpret_cast<float4*>(g_agg);
    a4[(size_t)w * D4 + lane] = make_float4(acc0 * inv, acc1 * inv, acc2 * inv, acc3 * inv);
}

// ---------------- kernel: fused dual-linear GEMM (f32x2 FMA, weights via L1) ----------------
// out[n,:] = g_bias + [feat[n] ; mean[n]] @ Wcat^T
// 64 nodes x 128 cols per block, 256 threads, thread tile = 8 rows x 4 cols.
// Smem holds only the transposed Z tile -> 2 blocks/SM; weights stream from L1.
__global__ void __launch_bounds__(256, 2)
gemm_kernel(const float* __restrict__ feat,
            float* __restrict__ out,
            int n_nodes) {
    extern __shared__ float Zt[];              // [K_TOT][ZT_STRIDE]

    const int tid = threadIdx.x;
    const int base = blockIdx.x * BM;

    // --- stage Z transposed: Zt[k][r] ---
    const float4* feat4 = reinterpret_cast<const float4*>(feat);
    const float4* agg4  = reinterpret_cast<const float4*>(g_agg);
    for (int i = tid; i < BM * D4; i += blockDim.x) {
        int r  = i & 63;
        int c4 = i >> 6;
        int n = base + r;
        float4 f = make_float4(0.f, 0.f, 0.f, 0.f);
        float4 a = f;
        if (n < n_nodes) {
            f = __ldg(&feat4[(size_t)n * D4 + c4]);
            a = agg4[(size_t)n * D4 + c4];
        }
        int k = c4 * 4;
        Zt[(k + 0) * ZT_STRIDE + r] = f.x;
        Zt[(k + 1) * ZT_STRIDE + r] = f.y;
        Zt[(k + 2) * ZT_STRIDE + r] = f.z;
        Zt[(k + 3) * ZT_STRIDE + r] = f.w;
        Zt[(k + 0 + D) * ZT_STRIDE + r] = a.x;
        Zt[(k + 1 + D) * ZT_STRIDE + r] = a.y;
        Zt[(k + 2 + D) * ZT_STRIDE + r] = a.z;
        Zt[(k + 3 + D) * ZT_STRIDE + r] = a.w;
    }
    __syncthreads();

    const int lane = tid & 31;
    const int trow = tid >> 5;                 // warp-uniform -> Z loads broadcast
    const int c0 = lane * 4;

    unsigned long long acc[4][4];
    #pragma unroll
    for (int p = 0; p < 4; p++)
        #pragma unroll
        for (int j = 0; j < 4; j++) acc[p][j] = 0ull;

    const float* zbase = &Zt[trow * 8];
    const float4* wp = reinterpret_cast<const float4*>(g_wt + c0);   // stride 32 float4 per k

    // software-pipelined mainloop: prefetch k+1 while computing k
    float4 wv = __ldg(wp);
    ulonglong2 z0 = reinterpret_cast<const ulonglong2*>(zbase)[0];
    ulonglong2 z1 = reinterpret_cast<const ulonglong2*>(zbase)[1];

    #pragma unroll 4
    for (int k = 0; k < K_TOT - 1; k++) {
        float4 wn = __ldg(wp + (k + 1) * (D / 4));
        const ulonglong2* zp = reinterpret_cast<const ulonglong2*>(zbase + (k + 1) * ZT_STRIDE);
        ulonglong2 z0n = zp[0];
        ulonglong2 z1n = zp[1];

        unsigned long long wd0 = pack2_dup(wv.x);
        unsigned long long wd1 = pack2_dup(wv.y);
        unsigned long long wd2 = pack2_dup(wv.z);
        unsigned long long wd3 = pack2_dup(wv.w);
        ffma2(acc[0][0], z0.x, wd0); ffma2(acc[0][1], z0.x, wd1);
        ffma2(acc[0][2], z0.x, wd2); ffma2(acc[0][3], z0.x, wd3);
        ffma2(acc[1][0], z0.y, wd0); ffma2(acc[1][1], z0.y, wd1);
        ffma2(acc[1][2], z0.y, wd2); ffma2(acc[1][3], z0.y, wd3);
        ffma2(acc[2][0], z1.x, wd0); ffma2(acc[2][1], z1.x, wd1);
        ffma2(acc[2][2], z1.x, wd2); ffma2(acc[2][3], z1.x, wd3);
        ffma2(acc[3][0], z1.y, wd0); ffma2(acc[3][1], z1.y, wd1);
        ffma2(acc[3][2], z1.y, wd2); ffma2(acc[3][3], z1.y, wd3);

        wv = wn; z0 = z0n; z1 = z1n;
    }
    {   // last k
        unsigned long long wd0 = pack2_dup(wv.x);
        unsigned long long wd1 = pack2_dup(wv.y);
        unsigned long long wd2 = pack2_dup(wv.z);
        unsigned long long wd3 = pack2_dup(wv.w);
        ffma2(acc[0][0], z0.x, wd0); ffma2(acc[0][1], z0.x, wd1);
        ffma2(acc[0][2], z0.x, wd2); ffma2(acc[0][3], z0.x, wd3);
        ffma2(acc[1][0], z0.y, wd0); ffma2(acc[1][1], z0.y, wd1);
        ffma2(acc[1][2], z0.y, wd2); ffma2(acc[1][3], z0.y, wd3);
        ffma2(acc[2][0], z1.x, wd0); ffma2(acc[2][1], z1.x, wd1);
        ffma2(acc[2][2], z1.x, wd2); ffma2(acc[2][3], z1.x, wd3);
        ffma2(acc[3][0], z1.y, wd0); ffma2(acc[3][1], z1.y, wd1);
        ffma2(acc[3][2], z1.y, wd2); ffma2(acc[3][3], z1.y, wd3);
    }

    // --- epilogue: bias + store ---
    float4 bias = *reinterpret_cast<const float4*>(&g_bias[c0]);

    float4* out4 = reinterpret_cast<float4*>(out);
    #pragma unroll
    for (int p = 0; p < 4; p++) {
        float lo0, hi0, lo1, hi1, lo2, hi2, lo3, hi3;
        unpack2(acc[p][0], lo0, hi0);
        unpack2(acc[p][1], lo1, hi1);
        unpack2(acc[p][2], lo2, hi2);
        unpack2(acc[p][3], lo3, hi3);
        int r0 = base + trow * 8 + 2 * p;
        if (r0 < n_nodes)
            out4[(size_t)r0 * D4 + lane] =
                make_float4(lo0 + bias.x, lo1 + bias.y, lo2 + bias.z, lo3 + bias.w);
        if (r0 + 1 < n_nodes)
            out4[(size_t)(r0 + 1) * D4 + lane] =
                make_float4(hi0 + bias.x, hi1 + bias.y, hi2 + bias.z, hi3 + bias.w);
    }
}

// ---------------- launch ----------------
extern "C" void kernel_launch(void* const* d_in, const int* in_sizes, int n_in,
                              void* d_out, int out_size) {
    const float* feat    = (const float*)d_in[0];
    const int*   src     = (const int*)  d_in[1];
    const int*   dst     = (const int*)  d_in[2];
    const float* W_self  = (const float*)d_in[3];
    const float* b_self  = (const float*)d_in[4];
    const float* W_neigh = (const float*)d_in[5];
    const float* b_neigh = (const float*)d_in[6];
    float* out = (float*)d_out;

    const int n_nodes = in_sizes[0] / D;
    const int n_edges = in_sizes[1];

    // independent prep
    zero_kernel<<<(n_nodes + 255) / 256, 256>>>(n_nodes);
    convert_kernel<<<(n_nodes * (D / 2) + 255) / 256, 256>>>(feat, n_nodes * (D / 2));
    prep_kernel<<<(D * D + 255) / 256, 256>>>(W_self, W_neigh, b_self, b_neigh);

    // bucket fill (thread per edge)
    fill_kernel<<<(n_edges + 255) / 256, 256>>>(src, dst, n_edges);

    // pull aggregation -> g_agg = neighbor mean
    {
        int warps_per_block = 256 / 32;
        int blocks = (n_nodes + warps_per_block - 1) / warps_per_block;
        aggregate_kernel<<<blocks, 256>>>(feat, src, dst, n_nodes, n_edges);
    }

    // fused GEMM
    {
        size_t smem = (size_t)(K_TOT * ZT_STRIDE) * sizeof(float);   // 69632 B
        cudaFuncSetAttribute(gemm_kernel,
                             cudaFuncAttributeMaxDynamicSharedMemorySize, (int)smem);
        int blocks = (n_nodes + BM - 1) / BM;
        gemm_kernel<<<blocks, 256, smem>>>(feat, out, n_nodes);
    }
}

// round 8
// speedup vs baseline: 1.2533x; 1.2533x over previous
#include <cuda_runtime.h>
#include <cuda_bf16.h>

// Problem constants: N=50000 nodes, E=1.6M edges, D_in=D_out=128.
#define D 128
#define D4 (D / 4)              // 32 float4 per row
#define MAX_NODES 50048
#define CAP 128                 // bucket capacity (Poisson(32); overflow astronomically rare)
#define K_TOT 256               // concat [feat ; mean_neigh]
#define BM 64                   // nodes per block in GEMM
#define WT_STRIDE 132           // padded row stride, transposed weights (528B, 16B-aligned)
#define ZT_STRIDE 68            // padded row stride, transposed Z (272B, 16B-aligned)
#define GEMM_THREADS 512

// ---------------- scratch (device globals) ----------------
__device__ float          g_agg[MAX_NODES * D];       // neighbor mean
__device__ int            g_cnt[MAX_NODES];           // in-degree
__device__ int            g_bucket[MAX_NODES * CAP];  // per-node src ids
__device__ __nv_bfloat16  g_featbf[MAX_NODES * D];    // bf16 copy of feat (gather operand)

// ---------------- packed f32x2 helpers ----------------
__device__ __forceinline__ unsigned long long pack2_dup(float x) {
    unsigned long long r;
    asm("mov.b64 %0, {%1, %1};" : "=l"(r) : "f"(x));
    return r;
}
__device__ __forceinline__ void ffma2(unsigned long long& acc,
                                      unsigned long long a, unsigned long long b) {
    asm("fma.rn.f32x2 %0, %1, %2, %0;" : "+l"(acc) : "l"(a), "l"(b));
}
__device__ __forceinline__ void unpack2(unsigned long long v, float& lo, float& hi) {
    asm("mov.b64 {%0, %1}, %2;" : "=f"(lo), "=f"(hi) : "l"(v));
}

// ---------------- kernel: zero in-degree counters ----------------
__global__ void zero_kernel(int n_cnt) {
    int i = blockIdx.x * blockDim.x + threadIdx.x;
    if (i < n_cnt) g_cnt[i] = 0;
}

// ---------------- kernel: convert feat -> bf16 ----------------
__global__ void convert_kernel(const float* __restrict__ feat, int n_f2) {
    int i = blockIdx.x * blockDim.x + threadIdx.x;
    if (i >= n_f2) return;
    float2 f = reinterpret_cast<const float2*>(feat)[i];
    reinterpret_cast<__nv_bfloat162*>(g_featbf)[i] = __float22bfloat162_rn(f);
}

// ---------------- kernel: fill per-dst buckets (4 edges/thread, MLP=4) ----------------
__global__ void fill_kernel(const int* __restrict__ src,
                            const int* __restrict__ dst,
                            int n_edges) {
    int g = blockIdx.x * blockDim.x + threadIdx.x;
    int e0 = g * 4;
    if (e0 >= n_edges) return;

    int s[4], d[4];
    if (e0 + 3 < n_edges) {
        int4 sv = *reinterpret_cast<const int4*>(src + e0);
        int4 dv = *reinterpret_cast<const int4*>(dst + e0);
        s[0] = sv.x; s[1] = sv.y; s[2] = sv.z; s[3] = sv.w;
        d[0] = dv.x; d[1] = dv.y; d[2] = dv.z; d[3] = dv.w;
        // 4 independent atomic chains in flight
        int p0 = atomicAdd(&g_cnt[d[0]], 1);
        int p1 = atomicAdd(&g_cnt[d[1]], 1);
        int p2 = atomicAdd(&g_cnt[d[2]], 1);
        int p3 = atomicAdd(&g_cnt[d[3]], 1);
        if (p0 < CAP) g_bucket[d[0] * CAP + p0] = s[0];
        if (p1 < CAP) g_bucket[d[1] * CAP + p1] = s[1];
        if (p2 < CAP) g_bucket[d[2] * CAP + p2] = s[2];
        if (p3 < CAP) g_bucket[d[3] * CAP + p3] = s[3];
    } else {
        for (int e = e0; e < n_edges; e++) {
            int ss = src[e], dd = dst[e];
            int pos = atomicAdd(&g_cnt[dd], 1);
            if (pos < CAP) g_bucket[dd * CAP + pos] = ss;
        }
    }
    // pos >= CAP handled by rescan fallback in aggregate_kernel (never in practice)
}

// ---------------- kernel: warp-per-node pull aggregation (bf16 gather, fp32 accum) ----------------
__global__ void aggregate_kernel(const float* __restrict__ feat,
                                 const int* __restrict__ src,
                                 const int* __restrict__ dst,
                                 int n_nodes, int n_edges) {
    int w = (blockIdx.x * blockDim.x + threadIdx.x) >> 5;
    if (w >= n_nodes) return;
    int lane = threadIdx.x & 31;

    int c = g_cnt[w];
    float acc0 = 0.f, acc1 = 0.f, acc2 = 0.f, acc3 = 0.f;

    if (c <= CAP) {
        const uint2* fb = reinterpret_cast<const uint2*>(g_featbf);  // uint2 = 4 bf16 cols
        const int* bk = &g_bucket[w * CAP];
        for (int i0 = 0; i0 < c; i0 += 32) {
            int take = min(32, c - i0);
            int my = (lane < take) ? bk[i0 + lane] : 0;
            #pragma unroll 4
            for (int j = 0; j < take; j++) {
                int s = __shfl_sync(0xffffffffu, my, j);
                uint2 v = __ldg(&fb[(size_t)s * 32 + lane]);
                float2 p0 = __bfloat1622float2(*reinterpret_cast<__nv_bfloat162*>(&v.x));
                float2 p1 = __bfloat1622float2(*reinterpret_cast<__nv_bfloat162*>(&v.y));
                acc0 += p0.x; acc1 += p0.y; acc2 += p1.x; acc3 += p1.y;
            }
        }
    } else {
        // correctness fallback (statistically never): rescan full edge list, fp32 gather
        const float4* f4 = reinterpret_cast<const float4*>(feat);
        for (int e = 0; e < n_edges; e++) {
            if (dst[e] == w) {
                float4 v = f4[(size_t)src[e] * D4 + lane];
                acc0 += v.x; acc1 += v.y; acc2 += v.z; acc3 += v.w;
            }
        }
    }

    float inv = 1.0f / fmaxf((float)c, 1.0f);
    float4* a4 = reinterpret_cast<float4*>(g_agg);
    a4[(size_t)w * D4 + lane] = make_float4(acc0 * inv, acc1 * inv, acc2 * inv, acc3 * inv);
}

// ---------------- kernel: fused dual-linear GEMM (f32x2 FMA, smem operands, 512 threads) ----------------
// out[n,:] = (b_self + b_neigh) + [feat[n] ; mean[n]] @ [W_self ; W_neigh]^T
// Block: 64 nodes x 128 cols, 512 threads (16 warps = 4/SMSP), thread tile = 4 rows x 4 cols.
__global__ void __launch_bounds__(GEMM_THREADS, 1)
gemm_kernel(const float* __restrict__ feat,
            const float* __restrict__ W_self,
            const float* __restrict__ b_self,
            const float* __restrict__ W_neigh,
            const float* __restrict__ b_neigh,
            float* __restrict__ out,
            int n_nodes) {
    extern __shared__ float smem[];
    float* Wt = smem;                          // [K_TOT][WT_STRIDE]  transposed weights
    float* Zt = smem + K_TOT * WT_STRIDE;      // [K_TOT][ZT_STRIDE]  transposed Z tile

    const int tid = threadIdx.x;
    const int base = blockIdx.x * BM;

    // --- stage transposed weights: Wt[k][o] = W[o][k] (coalesced gmem reads) ---
    for (int i = tid; i < D * D; i += GEMM_THREADS) {
        int o = i >> 7;
        int k = i & (D - 1);
        Wt[k * WT_STRIDE + o]       = W_self[i];
        Wt[(k + D) * WT_STRIDE + o] = W_neigh[i];
    }

    // --- stage Z transposed: Zt[k][r] (lane-varying r -> conflict-free smem writes) ---
    const float4* feat4 = reinterpret_cast<const float4*>(feat);
    const float4* agg4  = reinterpret_cast<const float4*>(g_agg);
    for (int i = tid; i < BM * D4; i += GEMM_THREADS) {
        int r  = i & 63;
        int c4 = i >> 6;
        int n = base + r;
        float4 f = make_float4(0.f, 0.f, 0.f, 0.f);
        float4 a = f;
        if (n < n_nodes) {
            f = __ldg(&feat4[(size_t)n * D4 + c4]);
            a = agg4[(size_t)n * D4 + c4];     // already the mean
        }
        int k = c4 * 4;
        Zt[(k + 0) * ZT_STRIDE + r] = f.x;
        Zt[(k + 1) * ZT_STRIDE + r] = f.y;
        Zt[(k + 2) * ZT_STRIDE + r] = f.z;
        Zt[(k + 3) * ZT_STRIDE + r] = f.w;
        Zt[(k + 0 + D) * ZT_STRIDE + r] = a.x;
        Zt[(k + 1 + D) * ZT_STRIDE + r] = a.y;
        Zt[(k + 2 + D) * ZT_STRIDE + r] = a.z;
        Zt[(k + 3 + D) * ZT_STRIDE + r] = a.w;
    }
    __syncthreads();

    const int lane = tid & 31;                 // 32 col-groups
    const int trow = tid >> 5;                 // 16 row-groups (warp-uniform -> Z broadcast)
    const int c0 = lane * 4;

    unsigned long long acc[2][4];              // [row-pair][col]
    #pragma unroll
    for (int p = 0; p < 2; p++)
        #pragma unroll
        for (int j = 0; j < 4; j++) acc[p][j] = 0ull;

    const float* zbase = &Zt[trow * 4];        // 4 rows = 2 f32x2 pairs = one 16B LDS

    #pragma unroll 8
    for (int k = 0; k < K_TOT; k++) {
        float4 wv = *reinterpret_cast<const float4*>(&Wt[k * WT_STRIDE + c0]);
        ulonglong2 z = *reinterpret_cast<const ulonglong2*>(zbase + k * ZT_STRIDE);

        unsigned long long wd0 = pack2_dup(wv.x);
        unsigned long long wd1 = pack2_dup(wv.y);
        unsigned long long wd2 = pack2_dup(wv.z);
        unsigned long long wd3 = pack2_dup(wv.w);

        ffma2(acc[0][0], z.x, wd0); ffma2(acc[0][1], z.x, wd1);
        ffma2(acc[0][2], z.x, wd2); ffma2(acc[0][3], z.x, wd3);
        ffma2(acc[1][0], z.y, wd0); ffma2(acc[1][1], z.y, wd1);
        ffma2(acc[1][2], z.y, wd2); ffma2(acc[1][3], z.y, wd3);
    }

    // --- epilogue: bias + store ---
    float4 bs = *reinterpret_cast<const float4*>(&b_self[c0]);
    float4 bn = *reinterpret_cast<const float4*>(&b_neigh[c0]);
    float4 bias = make_float4(bs.x + bn.x, bs.y + bn.y, bs.z + bn.z, bs.w + bn.w);

    float4* out4 = reinterpret_cast<float4*>(out);
    #pragma unroll
    for (int p = 0; p < 2; p++) {
        float lo0, hi0, lo1, hi1, lo2, hi2, lo3, hi3;
        unpack2(acc[p][0], lo0, hi0);
        unpack2(acc[p][1], lo1, hi1);
        unpack2(acc[p][2], lo2, hi2);
        unpack2(acc[p][3], lo3, hi3);
        int r0 = base + trow * 4 + 2 * p;
        if (r0 < n_nodes)
            out4[(size_t)r0 * D4 + lane] =
                make_float4(lo0 + bias.x, lo1 + bias.y, lo2 + bias.z, lo3 + bias.w);
        if (r0 + 1 < n_nodes)
            out4[(size_t)(r0 + 1) * D4 + lane] =
                make_float4(hi0 + bias.x, hi1 + bias.y, hi2 + bias.z, hi3 + bias.w);
    }
}

// ---------------- launch ----------------
extern "C" void kernel_launch(void* const* d_in, const int* in_sizes, int n_in,
                              void* d_out, int out_size) {
    const float* feat    = (const float*)d_in[0];
    const int*   src     = (const int*)  d_in[1];
    const int*   dst     = (const int*)  d_in[2];
    const float* W_self  = (const float*)d_in[3];
    const float* b_self  = (const float*)d_in[4];
    const float* W_neigh = (const float*)d_in[5];
    const float* b_neigh = (const float*)d_in[6];
    float* out = (float*)d_out;

    const int n_nodes = in_sizes[0] / D;
    const int n_edges = in_sizes[1];

    // prep (independent)
    zero_kernel<<<(n_nodes + 255) / 256, 256>>>(n_nodes);
    convert_kernel<<<(n_nodes * (D / 2) + 255) / 256, 256>>>(feat, n_nodes * (D / 2));

    // bucket fill: 4 edges per thread
    {
        int n_thr = (n_edges + 3) / 4;
        fill_kernel<<<(n_thr + 255) / 256, 256>>>(src, dst, n_edges);
    }

    // pull aggregation -> g_agg = neighbor mean
    {
        int warps_per_block = 256 / 32;
        int blocks = (n_nodes + warps_per_block - 1) / warps_per_block;
        aggregate_kernel<<<blocks, 256>>>(feat, src, dst, n_nodes, n_edges);
    }

    // fused GEMM
    {
        size_t smem = (size_t)(K_TOT * WT_STRIDE + K_TOT * ZT_STRIDE) * sizeof(float); // 204800 B
        cudaFuncSetAttribute(gemm_kernel,
                             cudaFuncAttributeMaxDynamicSharedMemorySize, (int)smem);
        int blocks = (n_nodes + BM - 1) / BM;
        gemm_kernel<<<blocks, GEMM_THREADS, smem>>>(feat, W_self, b_self, W_neigh, b_neigh,
                                                    out, n_nodes);
    }
}

// round 10
// speedup vs baseline: 1.2661x; 1.0102x over previous
#include <cuda_runtime.h>
#include <cuda_bf16.h>

// Problem constants: N=50000 nodes, E=1.6M edges, D_in=D_out=128.
#define D 128
#define D4 (D / 4)              // 32 float4 per row
#define MAX_NODES 50048
#define CAP 128                 // bucket capacity (Poisson(32); overflow astronomically rare)
#define K_TOT 256               // concat [feat ; mean_neigh]
#define BM 64                   // nodes per block in GEMM
#define WT_STRIDE 130           // Wt row stride: 8B-aligned, conflict-free reads, 2-way staging writes
#define ZT_STRIDE 64            // Zt row stride: broadcast reads, conflict-free staging writes
#define GEMM_THREADS 512

// ---------------- scratch (device globals) ----------------
__device__ float          g_agg[MAX_NODES * D];       // neighbor mean
__device__ int            g_cnt[MAX_NODES];           // in-degree
__device__ int            g_bucket[MAX_NODES * CAP];  // per-node src ids
__device__ __nv_bfloat16  g_featbf[MAX_NODES * D];    // bf16 feat copy; rows >= n_nodes are ZERO

// ---------------- packed f32x2 helpers ----------------
__device__ __forceinline__ unsigned long long pack2_dup(float x) {
    unsigned long long r;
    asm("mov.b64 %0, {%1, %1};" : "=l"(r) : "f"(x));
    return r;
}
__device__ __forceinline__ void ffma2(unsigned long long& acc,
                                      unsigned long long a, unsigned long long b) {
    asm("fma.rn.f32x2 %0, %1, %2, %0;" : "+l"(acc) : "l"(a), "l"(b));
}
__device__ __forceinline__ void addf32x2(unsigned long long& acc, unsigned long long a) {
    asm("add.rn.f32x2 %0, %0, %1;" : "+l"(acc) : "l"(a));
}
__device__ __forceinline__ void unpack2(unsigned long long v, float& lo, float& hi) {
    asm("mov.b64 {%0, %1}, %2;" : "=f"(lo), "=f"(hi) : "l"(v));
}
// Two bf16 packed in a uint32 -> packed f32x2 (exact: bf16 widen is a shift)
__device__ __forceinline__ unsigned long long bf2_to_f32x2(unsigned int v) {
    unsigned long long r;
    asm("{\n\t"
        ".reg .b32 lo, hi;\n\t"
        "shl.b32 lo, %1, 16;\n\t"
        "and.b32 hi, %1, 0xFFFF0000;\n\t"
        "mov.b64 %0, {lo, hi};\n\t"
        "}" : "=l"(r) : "r"(v));
    return r;
}

// ---------------- kernel: zero in-degree counters ----------------
__global__ void zero_kernel(int n_cnt) {
    int i = blockIdx.x * blockDim.x + threadIdx.x;
    if (i < n_cnt) g_cnt[i] = 0;
}

// ---------------- kernel: convert feat -> bf16 (+ zero the padding rows) ----------------
__global__ void convert_kernel(const float* __restrict__ feat, int n_f2) {
    int i = blockIdx.x * blockDim.x + threadIdx.x;
    if (i >= MAX_NODES * (D / 2)) return;
    __nv_bfloat162* fb2 = reinterpret_cast<__nv_bfloat162*>(g_featbf);
    if (i < n_f2) {
        float2 f = reinterpret_cast<const float2*>(feat)[i];
        fb2[i] = __float22bfloat162_rn(f);
    } else {
        fb2[i] = __nv_bfloat162{__nv_bfloat16(0.f), __nv_bfloat16(0.f)};  // dummy rows
    }
}

// ---------------- kernel: fill per-dst buckets (4 edges/thread, MLP=4) ----------------
__global__ void fill_kernel(const int* __restrict__ src,
                            const int* __restrict__ dst,
                            int n_edges) {
    int g = blockIdx.x * blockDim.x + threadIdx.x;
    int e0 = g * 4;
    if (e0 >= n_edges) return;

    if (e0 + 3 < n_edges) {
        int4 sv = *reinterpret_cast<const int4*>(src + e0);
        int4 dv = *reinterpret_cast<const int4*>(dst + e0);
        int p0 = atomicAdd(&g_cnt[dv.x], 1);
        int p1 = atomicAdd(&g_cnt[dv.y], 1);
        int p2 = atomicAdd(&g_cnt[dv.z], 1);
        int p3 = atomicAdd(&g_cnt[dv.w], 1);
        if (p0 < CAP) g_bucket[dv.x * CAP + p0] = sv.x;
        if (p1 < CAP) g_bucket[dv.y * CAP + p1] = sv.y;
        if (p2 < CAP) g_bucket[dv.z * CAP + p2] = sv.z;
        if (p3 < CAP) g_bucket[dv.w * CAP + p3] = sv.w;
    } else {
        for (int e = e0; e < n_edges; e++) {
            int ss = src[e], dd = dst[e];
            int pos = atomicAdd(&g_cnt[dd], 1);
            if (pos < CAP) g_bucket[dd * CAP + pos] = ss;
        }
    }
    // pos >= CAP handled by rescan fallback in aggregate_kernel (never in practice)
}

// ---------------- kernel: warp-per-node pull aggregation ----------------
// 2 edges per iteration: lanes 0-15 handle edge 2j, lanes 16-31 edge 2j+1.
// Each lane loads 16B (8 bf16); decode via shl/and (exact) into packed f32x2 accumulators.
__global__ void aggregate_kernel(const float* __restrict__ feat,
                                 const int* __restrict__ src,
                                 const int* __restrict__ dst,
                                 int n_nodes, int n_edges) {
    int w = (blockIdx.x * blockDim.x + threadIdx.x) >> 5;
    if (w >= n_nodes) return;
    int lane = threadIdx.x & 31;

    int c = g_cnt[w];

    if (c <= CAP) {
        const int half = lane >> 4;       // which edge of the pair
        const int lcol = lane & 15;       // 16 lanes cover one 256B row
        const uint4* fb = reinterpret_cast<const uint4*>(g_featbf);
        const int* bk = &g_bucket[w * CAP];

        unsigned long long acc0 = 0ull, acc1 = 0ull, acc2 = 0ull, acc3 = 0ull;

        for (int i0 = 0; i0 < c; i0 += 32) {
            int idx = i0 + lane;
            int my = (idx < c) ? bk[idx] : n_nodes;     // dummy zero row
            int rem = c - i0;
            int pairs = min(16, (rem + 1) >> 1);
            for (int jj = 0; jj < pairs; jj++) {
                int s = __shfl_sync(0xffffffffu, my, 2 * jj + half);
                uint4 v = __ldg(&fb[(size_t)s * 16 + lcol]);
                addf32x2(acc0, bf2_to_f32x2(v.x));
                addf32x2(acc1, bf2_to_f32x2(v.y));
                addf32x2(acc2, bf2_to_f32x2(v.z));
                addf32x2(acc3, bf2_to_f32x2(v.w));
            }
        }

        // combine the two halves (edge parity split): xor-16 shuffle + f32x2 add
        addf32x2(acc0, __shfl_xor_sync(0xffffffffu, acc0, 16));
        addf32x2(acc1, __shfl_xor_sync(0xffffffffu, acc1, 16));
        addf32x2(acc2, __shfl_xor_sync(0xffffffffu, acc2, 16));
        addf32x2(acc3, __shfl_xor_sync(0xffffffffu, acc3, 16));

        float inv = 1.0f / fmaxf((float)c, 1.0f);
        // lane covers cols lcol*8 + half*4 .. +4 (every lane holds full sums after xor-add)
        float a, b, cc, dd;
        if (half == 0) {
            float l0, h0, l1, h1;
            unpack2(acc0, l0, h0); unpack2(acc1, l1, h1);
            a = l0; b = h0; cc = l1; dd = h1;
        } else {
            float l2, h2, l3, h3;
            unpack2(acc2, l2, h2); unpack2(acc3, l3, h3);
            a = l2; b = h2; cc = l3; dd = h3;
        }
        float4* a4 = reinterpret_cast<float4*>(g_agg);
        a4[(size_t)w * D4 + lcol * 2 + half] =
            make_float4(a * inv, b * inv, cc * inv, dd * inv);
    } else {
        // correctness fallback (statistically never): rescan full edge list, fp32 gather
        float acc0 = 0.f, acc1 = 0.f, acc2 = 0.f, acc3 = 0.f;
        const float4* f4 = reinterpret_cast<const float4*>(feat);
        for (int e = 0; e < n_edges; e++) {
            if (dst[e] == w) {
                float4 v = f4[(size_t)src[e] * D4 + lane];
                acc0 += v.x; acc1 += v.y; acc2 += v.z; acc3 += v.w;
            }
        }
        float inv = 1.0f / fmaxf((float)c, 1.0f);
        float4* a4 = reinterpret_cast<float4*>(g_agg);
        a4[(size_t)w * D4 + lane] = make_float4(acc0 * inv, acc1 * inv, acc2 * inv, acc3 * inv);
    }
}

// ---------------- kernel: fused dual-linear GEMM (f32x2 FMA, crossbar-light tiling) ----------------
// out[n,:] = (b_self+b_neigh) + [feat[n] ; mean[n]] @ [W_self ; W_neigh]^T
// 512 threads, 16 warps: warp = 8 rows x 64 cols (8 row-groups x 2 col-groups), lane = 2 cols.
// Per warp per k: Wt 256B lane-varying (conflict-free) + Zt 32B broadcast -> ~3-4 wf < fma floor.
__global__ void __launch_bounds__(GEMM_THREADS, 1)
gemm_kernel(const float* __restrict__ feat,
            const float* __restrict__ W_self,
            const float* __restrict__ b_self,
            const float* __restrict__ W_neigh,
            const float* __restrict__ b_neigh,
            float* __restrict__ out,
            int n_nodes) {
    extern __shared__ float smem[];
    float* Wt = smem;                          // [K_TOT][WT_STRIDE]
    float* Zt = smem + K_TOT * WT_STRIDE;      // [K_TOT][ZT_STRIDE]

    const int tid = threadIdx.x;
    const int base = blockIdx.x * BM;

    // --- stage transposed weights: Wt[k][o] = W[o][k] (coalesced gmem; 2-way smem conflicts) ---
    for (int i = tid; i < D * D; i += GEMM_THREADS) {
        int o = i >> 7;
        int k = i & (D - 1);
        Wt[k * WT_STRIDE + o]       = W_self[i];
        Wt[(k + D) * WT_STRIDE + o] = W_neigh[i];
    }

    // --- stage Z transposed: Zt[k][r] (conflict-free writes) ---
    const float4* feat4 = reinterpret_cast<const float4*>(feat);
    const float4* agg4  = reinterpret_cast<const float4*>(g_agg);
    for (int i = tid; i < BM * D4; i += GEMM_THREADS) {
        int r  = i & 63;
        int c4 = i >> 6;
        int n = base + r;
        float4 f = make_float4(0.f, 0.f, 0.f, 0.f);
        float4 a = f;
        if (n < n_nodes) {
            f = __ldg(&feat4[(size_t)n * D4 + c4]);
            a = agg4[(size_t)n * D4 + c4];     // already the mean
        }
        int k = c4 * 4;
        Zt[(k + 0) * ZT_STRIDE + r] = f.x;
        Zt[(k + 1) * ZT_STRIDE + r] = f.y;
        Zt[(k + 2) * ZT_STRIDE + r] = f.z;
        Zt[(k + 3) * ZT_STRIDE + r] = f.w;
        Zt[(k + 0 + D) * ZT_STRIDE + r] = a.x;
        Zt[(k + 1 + D) * ZT_STRIDE + r] = a.y;
        Zt[(k + 2 + D) * ZT_STRIDE + r] = a.z;
        Zt[(k + 3 + D) * ZT_STRIDE + r] = a.w;
    }
    __syncthreads();

    const int lane = tid & 31;
    const int wid  = tid >> 5;                 // 16 warps
    const int wrow = (wid >> 1) * 8;           // 8-row group
    const int wcol = (wid & 1) * 64;           // 64-col group
    const int c0   = wcol + lane * 2;          // 2 cols per lane

    unsigned long long acc[4][2];              // [row-pair][col]
    #pragma unroll
    for (int p = 0; p < 4; p++) { acc[p][0] = 0ull; acc[p][1] = 0ull; }

    const float* zb = Zt + wrow;               // broadcast source
    const float* wb = Wt + c0;

    #pragma unroll 4
    for (int k = 0; k < K_TOT; k++) {
        float2 wv = *reinterpret_cast<const float2*>(wb + k * WT_STRIDE);
        ulonglong2 zA = *reinterpret_cast<const ulonglong2*>(zb + k * ZT_STRIDE);
        ulonglong2 zB = *reinterpret_cast<const ulonglong2*>(zb + k * ZT_STRIDE + 4);

        unsigned long long w0 = pack2_dup(wv.x);
        unsigned long long w1 = pack2_dup(wv.y);

        ffma2(acc[0][0], zA.x, w0); ffma2(acc[0][1], zA.x, w1);
        ffma2(acc[1][0], zA.y, w0); ffma2(acc[1][1], zA.y, w1);
        ffma2(acc[2][0], zB.x, w0); ffma2(acc[2][1], zB.x, w1);
        ffma2(acc[3][0], zB.y, w0); ffma2(acc[3][1], zB.y, w1);
    }

    // --- epilogue: bias + store (float2 per row; warp covers 256B per row segment) ---
    float2 bs = *reinterpret_cast<const float2*>(&b_self[c0]);
    float2 bn = *reinterpret_cast<const float2*>(&b_neigh[c0]);
    float2 bias = make_float2(bs.x + bn.x, bs.y + bn.y);

    #pragma unroll
    for (int p = 0; p < 4; p++) {
        float lo0, hi0, lo1, hi1;
        unpack2(acc[p][0], lo0, hi0);          // rows 2p, 2p+1 for col c0
        unpack2(acc[p][1], lo1, hi1);          // rows 2p, 2p+1 for col c0+1
        int r0 = base + wrow + 2 * p;
        if (r0 < n_nodes)
            *reinterpret_cast<float2*>(out + (size_t)r0 * D + c0) =
                make_float2(lo0 + bias.x, lo1 + bias.y);
        if (r0 + 1 < n_nodes)
            *reinterpret_cast<float2*>(out + (size_t)(r0 + 1) * D + c0) =
                make_float2(hi0 + bias.x, hi1 + bias.y);
    }
}

// ---------------- launch ----------------
extern "C" void kernel_launch(void* const* d_in, const int* in_sizes, int n_in,
                              void* d_out, int out_size) {
    const float* feat    = (const float*)d_in[0];
    const int*   src     = (const int*)  d_in[1];
    const int*   dst     = (const int*)  d_in[2];
    const float* W_self  = (const float*)d_in[3];
    const float* b_self  = (const float*)d_in[4];
    const float* W_neigh = (const float*)d_in[5];
    const float* b_neigh = (const float*)d_in[6];
    float* out = (float*)d_out;

    const int n_nodes = in_sizes[0] / D;
    const int n_edges = in_sizes[1];

    // prep (independent)
    zero_kernel<<<(n_nodes + 255) / 256, 256>>>(n_nodes);
    convert_kernel<<<(MAX_NODES * (D / 2) + 255) / 256, 256>>>(feat, n_nodes * (D / 2));

    // bucket fill: 4 edges per thread
    {
        int n_thr = (n_edges + 3) / 4;
        fill_kernel<<<(n_thr + 255) / 256, 256>>>(src, dst, n_edges);
    }

    // pull aggregation -> g_agg = neighbor mean
    {
        int warps_per_block = 256 / 32;
        int blocks = (n_nodes + warps_per_block - 1) / warps_per_block;
        aggregate_kernel<<<blocks, 256>>>(feat, src, dst, n_nodes, n_edges);
    }

    // fused GEMM
    {
        size_t smem = (size_t)(K_TOT * WT_STRIDE + K_TOT * ZT_STRIDE) * sizeof(float); // 198656 B
        cudaFuncSetAttribute(gemm_kernel,
                             cudaFuncAttributeMaxDynamicSharedMemorySize, (int)smem);
        int blocks = (n_nodes + BM - 1) / BM;
        gemm_kernel<<<blocks, GEMM_THREADS, smem>>>(feat, W_self, b_self, W_neigh, b_neigh,
                                                    out, n_nodes);
    }
}

// round 12
// speedup vs baseline: 1.9516x; 1.5414x over previous
#include <cuda_runtime.h>
#include <cuda_bf16.h>
#include <cstdint>

// Problem constants: N=50000 nodes, E=1.6M edges, D_in=D_out=128.
#define D 128
#define D4 (D / 4)
#define MAX_NODES 50048          // 391 * 128
#define CAP 128                  // bucket capacity (Poisson(32); overflow astronomically rare)
#define K_TOT 256                // concat [feat ; mean_neigh]

// GEMM smem: 4 tiles [128 rows][272 B] + bias
#define ROWB      272            // 128 bf16 = 256B payload + 16B pad (banks (4r+c): conflict-free frags)
#define TILE_B    (128 * ROWB)   // 34816
#define SM_AH     0
#define SM_AL     (SM_AH + TILE_B)
#define SM_BH     (SM_AL + TILE_B)
#define SM_BL     (SM_BH + TILE_B)
#define SM_BIAS   (SM_BL + TILE_B)
#define SM_TOTAL  (SM_BIAS + 512)          // 139776 B

// ---------------- scratch (device globals; no allocation allowed) ----------------
__device__ __nv_bfloat16 g_zh[MAX_NODES * K_TOT];   // Z hi  [node][k] (k<128 feat, k>=128 mean)
__device__ __nv_bfloat16 g_zl[MAX_NODES * K_TOT];   // Z lo residual
__device__ __nv_bfloat16 g_wh[D * K_TOT];           // Wcat hi [o][k]
__device__ __nv_bfloat16 g_wl[D * K_TOT];           // Wcat lo residual
__device__ int           g_cnt[MAX_NODES];
__device__ int           g_bucket[MAX_NODES * CAP];

// ---------------- mma.sync helper (sm_80 PTX; HMMA fallback on sm_103) ----------------
__device__ __forceinline__ void mma_bf16(float* d, const unsigned* a, const unsigned* b) {
    asm volatile(
        "mma.sync.aligned.m16n8k16.row.col.f32.bf16.bf16.f32 "
        "{%0,%1,%2,%3}, {%4,%5,%6,%7}, {%8,%9}, {%0,%1,%2,%3};"
        : "+f"(d[0]), "+f"(d[1]), "+f"(d[2]), "+f"(d[3])
        : "r"(a[0]), "r"(a[1]), "r"(a[2]), "r"(a[3]), "r"(b[0]), "r"(b[1]));
}

// ---------------- kernel: zero in-degree counters (incl. pad rows) ----------------
__global__ void zero_kernel() {
    int i = blockIdx.x * blockDim.x + threadIdx.x;
    if (i < MAX_NODES) g_cnt[i] = 0;
}

// ---------------- kernel: feat -> (zh, zl) first half; pad rows zeroed ----------------
__global__ void convert_kernel(const float* __restrict__ feat, int n_f2) {
    int i = blockIdx.x * blockDim.x + threadIdx.x;      // float2 units, 64 per feat-half row
    if (i >= MAX_NODES * 64) return;
    int node = i >> 6;
    int c2   = i & 63;
    __nv_bfloat162* zh2 = reinterpret_cast<__nv_bfloat162*>(g_zh);
    __nv_bfloat162* zl2 = reinterpret_cast<__nv_bfloat162*>(g_zl);
    int idx = node * 128 + c2;                          // bf162 units; full row = 128 bf162
    if (i < n_f2) {
        float2 f = reinterpret_cast<const float2*>(feat)[i];
        __nv_bfloat16 hx = __float2bfloat16_rn(f.x);
        __nv_bfloat16 hy = __float2bfloat16_rn(f.y);
        zh2[idx] = __halves2bfloat162(hx, hy);
        zl2[idx] = __floats2bfloat162_rn(f.x - __bfloat162float(hx),
                                         f.y - __bfloat162float(hy));
    } else {
        __nv_bfloat162 z = __floats2bfloat162_rn(0.f, 0.f);
        zh2[idx] = z; zl2[idx] = z;
    }
}

// ---------------- kernel: weight hi/lo split, [o][k] concat layout ----------------
__global__ void prepw_kernel(const float* __restrict__ W_self,
                             const float* __restrict__ W_neigh) {
    int i = blockIdx.x * blockDim.x + threadIdx.x;      // 0 .. 32767
    if (i >= D * K_TOT) return;
    int o = i >> 8;
    int k = i & 255;
    float w = (k < D) ? W_self[o * D + k] : W_neigh[o * D + (k - D)];
    __nv_bfloat16 h = __float2bfloat16_rn(w);
    g_wh[i] = h;
    g_wl[i] = __float2bfloat16_rn(w - __bfloat162float(h));
}

// ---------------- kernel: fill per-dst buckets (4 edges/thread) ----------------
__global__ void fill_kernel(const int* __restrict__ src,
                            const int* __restrict__ dst,
                            int n_edges) {
    int g = blockIdx.x * blockDim.x + threadIdx.x;
    int e0 = g * 4;
    if (e0 >= n_edges) return;
    if (e0 + 3 < n_edges) {
        int4 sv = *reinterpret_cast<const int4*>(src + e0);
        int4 dv = *reinterpret_cast<const int4*>(dst + e0);
        int p0 = atomicAdd(&g_cnt[dv.x], 1);
        int p1 = atomicAdd(&g_cnt[dv.y], 1);
        int p2 = atomicAdd(&g_cnt[dv.z], 1);
        int p3 = atomicAdd(&g_cnt[dv.w], 1);
        if (p0 < CAP) g_bucket[dv.x * CAP + p0] = sv.x;
        if (p1 < CAP) g_bucket[dv.y * CAP + p1] = sv.y;
        if (p2 < CAP) g_bucket[dv.z * CAP + p2] = sv.z;
        if (p3 < CAP) g_bucket[dv.w * CAP + p3] = sv.w;
    } else {
        for (int e = e0; e < n_edges; e++) {
            int ss = src[e], dd = dst[e];
            int pos = atomicAdd(&g_cnt[dd], 1);
            if (pos < CAP) g_bucket[dd * CAP + pos] = ss;
        }
    }
}

// ---------------- kernel: warp-per-node pull aggregation (R8-style bf16 gather) ----------------
// Gathers bf16 feat rows from g_zh first half; writes mean hi/lo into Z second half.
__global__ void aggregate_kernel(int n_nodes) {
    int w = (blockIdx.x * blockDim.x + threadIdx.x) >> 5;
    if (w >= MAX_NODES) return;
    int lane = threadIdx.x & 31;

    int c = g_cnt[w];                       // 0 for pad rows
    if (c > CAP) return;                    // handled exactly by fallback kernel

    float acc0 = 0.f, acc1 = 0.f, acc2 = 0.f, acc3 = 0.f;
    const uint2* fb = reinterpret_cast<const uint2*>(g_zh);  // row = 64 uint2; feat half = first 32
    const int* bk = &g_bucket[w * CAP];
    for (int i0 = 0; i0 < c; i0 += 32) {
        int take = min(32, c - i0);
        int my = (lane < take) ? bk[i0 + lane] : 0;
        #pragma unroll 4
        for (int j = 0; j < take; j++) {
            int s = __shfl_sync(0xffffffffu, my, j);
            uint2 v = __ldg(&fb[(size_t)s * 64 + lane]);     // 4 bf16 cols at 4*lane
            float2 p0 = __bfloat1622float2(*reinterpret_cast<__nv_bfloat162*>(&v.x));
            float2 p1 = __bfloat1622float2(*reinterpret_cast<__nv_bfloat162*>(&v.y));
            acc0 += p0.x; acc1 += p0.y; acc2 += p1.x; acc3 += p1.y;
        }
    }

    float inv = 1.0f / fmaxf((float)c, 1.0f);
    float m0 = acc0 * inv, m1 = acc1 * inv, m2 = acc2 * inv, m3 = acc3 * inv;

    __nv_bfloat16 h0 = __float2bfloat16_rn(m0);
    __nv_bfloat16 h1 = __float2bfloat16_rn(m1);
    __nv_bfloat16 h2 = __float2bfloat16_rn(m2);
    __nv_bfloat16 h3 = __float2bfloat16_rn(m3);
    __nv_bfloat162 hA = __halves2bfloat162(h0, h1);
    __nv_bfloat162 hB = __halves2bfloat162(h2, h3);
    __nv_bfloat162 lA = __floats2bfloat162_rn(m0 - __bfloat162float(h0),
                                              m1 - __bfloat162float(h1));
    __nv_bfloat162 lB = __floats2bfloat162_rn(m2 - __bfloat162float(h2),
                                              m3 - __bfloat162float(h3));
    uint2* zh = reinterpret_cast<uint2*>(g_zh);
    uint2* zl = reinterpret_cast<uint2*>(g_zl);
    zh[(size_t)w * 64 + 32 + lane] =
        make_uint2(*reinterpret_cast<unsigned int*>(&hA), *reinterpret_cast<unsigned int*>(&hB));
    zl[(size_t)w * 64 + 32 + lane] =
        make_uint2(*reinterpret_cast<unsigned int*>(&lA), *reinterpret_cast<unsigned int*>(&lB));
}

// Exact fallback for overflowed nodes (c > CAP): full edge rescan, fp32. Never fires in practice.
__global__ void aggregate_fallback_kernel(const float* __restrict__ feat,
                                          const int* __restrict__ src,
                                          const int* __restrict__ dst,
                                          int n_nodes, int n_edges) {
    int w = (blockIdx.x * blockDim.x + threadIdx.x) >> 5;
    if (w >= n_nodes) return;
    int c = g_cnt[w];
    if (c <= CAP) return;
    int lane = threadIdx.x & 31;
    float acc0 = 0.f, acc1 = 0.f, acc2 = 0.f, acc3 = 0.f;
    const float4* f4 = reinterpret_cast<const float4*>(feat);
    for (int e = 0; e < n_edges; e++) {
        if (dst[e] == w) {
            float4 v = f4[(size_t)src[e] * D4 + lane];
            acc0 += v.x; acc1 += v.y; acc2 += v.z; acc3 += v.w;
        }
    }
    float inv = 1.0f / (float)c;
    float m0 = acc0 * inv, m1 = acc1 * inv, m2 = acc2 * inv, m3 = acc3 * inv;
    __nv_bfloat16 h0 = __float2bfloat16_rn(m0);
    __nv_bfloat16 h1 = __float2bfloat16_rn(m1);
    __nv_bfloat16 h2 = __float2bfloat16_rn(m2);
    __nv_bfloat16 h3 = __float2bfloat16_rn(m3);
    __nv_bfloat162 hA = __halves2bfloat162(h0, h1);
    __nv_bfloat162 hB = __halves2bfloat162(h2, h3);
    __nv_bfloat162 lA = __floats2bfloat162_rn(m0 - __bfloat162float(h0),
                                              m1 - __bfloat162float(h1));
    __nv_bfloat162 lB = __floats2bfloat162_rn(m2 - __bfloat162float(h2),
                                              m3 - __bfloat162float(h3));
    uint2* zh = reinterpret_cast<uint2*>(g_zh);
    uint2* zl = reinterpret_cast<uint2*>(g_zl);
    zh[(size_t)w * 64 + 32 + lane] =
        make_uint2(*reinterpret_cast<unsigned int*>(&hA), *reinterpret_cast<unsigned int*>(&hB));
    zl[(size_t)w * 64 + 32 + lane] =
        make_uint2(*reinterpret_cast<unsigned int*>(&lA), *reinterpret_cast<unsigned int*>(&lB));
}

// ---------------- kernel: split-bf16 mma.sync GEMM ----------------
// Per CTA: 128 rows x 128 cols, K=256 in 2 chunks of 128.
// acc += Zh*Wh + Zl*Wh + Zh*Wl  (3 mma passes, shared fragments).
// 8 warps: warp tile 64 rows x 32 cols = 4 m-tiles x 4 n-tiles of m16n8k16.
__global__ void __launch_bounds__(256, 1)
gemm_kernel(const float* __restrict__ b_self,
            const float* __restrict__ b_neigh,
            float* __restrict__ out,
            int n_nodes) {
    extern __shared__ char sm[];
    const int tid  = threadIdx.x;
    const int lane = tid & 31;
    const int wid  = tid >> 5;
    const int base = blockIdx.x * 128;

    const int wm = (wid & 1) * 64;         // warp row base
    const int wn = (wid >> 1) * 32;        // warp col base
    const int qr = lane >> 2;              // 0..7
    const int qc = lane & 3;               // 0..3

    if (tid < 128)
        *reinterpret_cast<float*>(sm + SM_BIAS + tid * 4) = b_self[tid] + b_neigh[tid];

    float acc[4][4][4];
    #pragma unroll
    for (int mt = 0; mt < 4; mt++)
        #pragma unroll
        for (int nt = 0; nt < 4; nt++)
            #pragma unroll
            for (int r = 0; r < 4; r++) acc[mt][nt][r] = 0.f;

    const uint4* zh4 = reinterpret_cast<const uint4*>(g_zh);
    const uint4* zl4 = reinterpret_cast<const uint4*>(g_zl);
    const uint4* wh4 = reinterpret_cast<const uint4*>(g_wh);
    const uint4* wl4 = reinterpret_cast<const uint4*>(g_wl);

    #pragma unroll 1
    for (int chunk = 0; chunk < 2; chunk++) {
        // --- stage 4 tiles (row = 16 uint4 = 128 bf16 of this k-chunk) ---
        #pragma unroll
        for (int i = tid; i < 2048; i += 256) {
            int r = i >> 4;
            int c = i & 15;
            int so = r * ROWB + c * 16;
            size_t zi = (size_t)(base + r) * 32 + chunk * 16 + c;
            size_t wi = (size_t)r * 32 + chunk * 16 + c;
            *reinterpret_cast<uint4*>(sm + SM_AH + so) = __ldg(&zh4[zi]);
            *reinterpret_cast<uint4*>(sm + SM_AL + so) = __ldg(&zl4[zi]);
            *reinterpret_cast<uint4*>(sm + SM_BH + so) = __ldg(&wh4[wi]);
            *reinterpret_cast<uint4*>(sm + SM_BL + so) = __ldg(&wl4[wi]);
        }
        __syncthreads();

        // --- 8 k-steps of 16 ---
        #pragma unroll 2
        for (int ks = 0; ks < 8; ks++) {
            int kb = ks * 32 + qc * 4;     // byte offset of this thread's first b32 in a row

            unsigned ah[4][4], al[4][4];
            #pragma unroll
            for (int mt = 0; mt < 4; mt++) {
                int r0 = (wm + mt * 16 + qr) * ROWB;
                int r8 = r0 + 8 * ROWB;
                ah[mt][0] = *reinterpret_cast<const unsigned*>(sm + SM_AH + r0 + kb);
                ah[mt][1] = *reinterpret_cast<const unsigned*>(sm + SM_AH + r8 + kb);
                ah[mt][2] = *reinterpret_cast<const unsigned*>(sm + SM_AH + r0 + kb + 16);
                ah[mt][3] = *reinterpret_cast<const unsigned*>(sm + SM_AH + r8 + kb + 16);
                al[mt][0] = *reinterpret_cast<const unsigned*>(sm + SM_AL + r0 + kb);
                al[mt][1] = *reinterpret_cast<const unsigned*>(sm + SM_AL + r8 + kb);
                al[mt][2] = *reinterpret_cast<const unsigned*>(sm + SM_AL + r0 + kb + 16);
                al[mt][3] = *reinterpret_cast<const unsigned*>(sm + SM_AL + r8 + kb + 16);
            }
            unsigned bh[4][2], bl[4][2];
            #pragma unroll
            for (int nt = 0; nt < 4; nt++) {
                int n0 = (wn + nt * 8 + qr) * ROWB;
                bh[nt][0] = *reinterpret_cast<const unsigned*>(sm + SM_BH + n0 + kb);
                bh[nt][1] = *reinterpret_cast<const unsigned*>(sm + SM_BH + n0 + kb + 16);
                bl[nt][0] = *reinterpret_cast<const unsigned*>(sm + SM_BL + n0 + kb);
                bl[nt][1] = *reinterpret_cast<const unsigned*>(sm + SM_BL + n0 + kb + 16);
            }

            #pragma unroll
            for (int mt = 0; mt < 4; mt++)
                #pragma unroll
                for (int nt = 0; nt < 4; nt++) {
                    mma_bf16(acc[mt][nt], ah[mt], bh[nt]);
                    mma_bf16(acc[mt][nt], al[mt], bh[nt]);
                    mma_bf16(acc[mt][nt], ah[mt], bl[nt]);
                }
        }
        __syncthreads();
    }

    // --- epilogue: bias + direct float2 stores ---
    #pragma unroll
    for (int mt = 0; mt < 4; mt++) {
        int m0 = base + wm + mt * 16 + qr;
        #pragma unroll
        for (int nt = 0; nt < 4; nt++) {
            int n0 = wn + nt * 8 + 2 * qc;
            float2 bv = *reinterpret_cast<const float2*>(sm + SM_BIAS + n0 * 4);
            if (m0 < n_nodes)
                *reinterpret_cast<float2*>(out + (size_t)m0 * D + n0) =
                    make_float2(acc[mt][nt][0] + bv.x, acc[mt][nt][1] + bv.y);
            if (m0 + 8 < n_nodes)
                *reinterpret_cast<float2*>(out + (size_t)(m0 + 8) * D + n0) =
                    make_float2(acc[mt][nt][2] + bv.x, acc[mt][nt][3] + bv.y);
        }
    }
}

// ---------------- launch ----------------
extern "C" void kernel_launch(void* const* d_in, const int* in_sizes, int n_in,
                              void* d_out, int out_size) {
    const float* feat    = (const float*)d_in[0];
    const int*   src     = (const int*)  d_in[1];
    const int*   dst     = (const int*)  d_in[2];
    const float* W_self  = (const float*)d_in[3];
    const float* b_self  = (const float*)d_in[4];
    const float* W_neigh = (const float*)d_in[5];
    const float* b_neigh = (const float*)d_in[6];
    float* out = (float*)d_out;

    const int n_nodes = in_sizes[0] / D;
    const int n_edges = in_sizes[1];

    zero_kernel<<<(MAX_NODES + 255) / 256, 256>>>();
    convert_kernel<<<(MAX_NODES * 64 + 255) / 256, 256>>>(feat, n_nodes * 64);
    prepw_kernel<<<(D * K_TOT + 255) / 256, 256>>>(W_self, W_neigh);

    {
        int n_thr = (n_edges + 3) / 4;
        fill_kernel<<<(n_thr + 255) / 256, 256>>>(src, dst, n_edges);
    }

    {
        int blocks = (MAX_NODES + 7) / 8;           // 8 warps/block
        aggregate_kernel<<<blocks, 256>>>(n_nodes);
        aggregate_fallback_kernel<<<(n_nodes + 7) / 8, 256>>>(feat, src, dst, n_nodes, n_edges);
    }

    {
        cudaFuncSetAttribute(gemm_kernel,
                             cudaFuncAttributeMaxDynamicSharedMemorySize, SM_TOTAL);
        int blocks = MAX_NODES / 128;               // 391
        gemm_kernel<<<blocks, 256, SM_TOTAL>>>(b_self, b_neigh, out, n_nodes);
    }
}